// round 16
// baseline (speedup 1.0000x reference)
#include <cuda_runtime.h>
#include <cuda_fp16.h>
#include <cstdint>

// ---------------------------------------------------------------------------
// Problem constants
// ---------------------------------------------------------------------------
#define BIMG   64
#define HWDIM  56
#define CCH    96
#define NHEADS 3
#define DHEAD  32
#define WIN    7
#define SHIFTW 3
#define NTOK   49
#define NWIN   64
#define NWTOT  (BIMG * NWIN)      // 4096
#define TOKENS (NWTOT * NTOK)     // 200704
#define MLPH   384
#define METAH  128
#define LN_EPS 1e-5f
#define LOG2E  1.4426950408889634f
#define MASKC  (-100.0f * 1.4426950408889634f)
#define GEMM_DSMEM 57344          // 2*(128*64 + 48*128) halves = 56KB

// ---------------------------------------------------------------------------
// Device scratch (static; cudaMalloc forbidden)
// q/k/v are TOKEN-MAJOR: [token][head*32 + dd]
// ---------------------------------------------------------------------------
__device__ __align__(16) __half g_h_h  [(size_t)TOKENS * CCH];
__device__ __align__(16) __half g_q_h  [(size_t)TOKENS * CCH];
__device__ __align__(16) __half g_k_h  [(size_t)TOKENS * CCH];
__device__ __align__(16) __half g_v_h  [(size_t)TOKENS * CCH];
__device__ __align__(16) __half g_o_h  [(size_t)TOKENS * CCH];
__device__ __align__(16) __half g_ln2_h[(size_t)TOKENS * CCH];
__device__ __align__(16) __half g_hid_h[(size_t)TOKENS * MLPH];
__device__ __align__(16) __half g_wqkv [96 * 288];
__device__ __align__(16) __half g_wproj[96 * 96];
__device__ __align__(16) __half g_wfc1 [96 * 384];
__device__ __align__(16) __half g_wfc2 [384 * 96];
__device__ __align__(16) float g_bias_pad[NHEADS * NTOK * 52];  // padded, *log2e
__device__ float g_pq[1568], g_pk[1568];
__device__ float g_sumq, g_sumk;

// ---------------------------------------------------------------------------
// Helpers
// ---------------------------------------------------------------------------
__device__ __forceinline__ float warp_sum(float v) {
#pragma unroll
    for (int o = 16; o; o >>= 1) v += __shfl_xor_sync(0xffffffffu, v, o);
    return v;
}
__device__ __forceinline__ float tanh_fast(float x) {
    float r;
    asm("tanh.approx.f32 %0, %1;" : "=f"(r) : "f"(x));
    return r;
}
__device__ __forceinline__ float gelu_tanh(float x) {
    float x3 = x * x * x;
    return 0.5f * x * (1.f + tanh_fast(0.7978845608028654f * (x + 0.044715f * x3)));
}
__device__ __forceinline__ uint32_t smem_u32(const void* p) {
    return (uint32_t)__cvta_generic_to_shared(p);
}
__device__ __forceinline__ void cp16(uint32_t dst, const void* src) {
    asm volatile("cp.async.cg.shared.global [%0], [%1], 16;" :: "r"(dst), "l"(src));
}
__device__ __forceinline__ void ldsm4(uint32_t& r0, uint32_t& r1, uint32_t& r2, uint32_t& r3, uint32_t a) {
    asm volatile("ldmatrix.sync.aligned.m8n8.x4.shared.b16 {%0,%1,%2,%3}, [%4];"
                 : "=r"(r0), "=r"(r1), "=r"(r2), "=r"(r3) : "r"(a));
}
__device__ __forceinline__ void ldsm4t(uint32_t& r0, uint32_t& r1, uint32_t& r2, uint32_t& r3, uint32_t a) {
    asm volatile("ldmatrix.sync.aligned.m8n8.x4.trans.shared.b16 {%0,%1,%2,%3}, [%4];"
                 : "=r"(r0), "=r"(r1), "=r"(r2), "=r"(r3) : "r"(a));
}
__device__ __forceinline__ void mma_f16(float c[4], const uint32_t a[4], const uint32_t b[2]) {
    asm volatile(
        "mma.sync.aligned.m16n8k16.row.col.f32.f16.f16.f32 "
        "{%0,%1,%2,%3}, {%4,%5,%6,%7}, {%8,%9}, {%0,%1,%2,%3};"
        : "+f"(c[0]), "+f"(c[1]), "+f"(c[2]), "+f"(c[3])
        : "r"(a[0]), "r"(a[1]), "r"(a[2]), "r"(a[3]), "r"(b[0]), "r"(b[1]));
}
__device__ __forceinline__ uint32_t pack_h2(float lo, float hi) {
    __half2 h = __floats2half2_rn(lo, hi);
    return (uint32_t)__half_as_ushort(__low2half(h)) |
           ((uint32_t)__half_as_ushort(__high2half(h)) << 16);
}
__device__ __forceinline__ uint32_t h2exp2_u32(uint32_t x) {
    uint32_t r;
    asm("ex2.approx.f16x2 %0, %1;" : "=r"(r) : "r"(x));
    return r;
}
__device__ __forceinline__ float2 h2_to_f2(uint32_t u) {
    float lo = __half2float(__ushort_as_half((unsigned short)(u & 0xffffu)));
    float hi = __half2float(__ushort_as_half((unsigned short)(u >> 16)));
    return make_float2(lo, hi);
}

// ---------------------------------------------------------------------------
// Weight fp32 -> fp16 conversion
// ---------------------------------------------------------------------------
__global__ void convw_kernel(const float* __restrict__ qkvw, const float* __restrict__ projw,
                             const float* __restrict__ fc1w, const float* __restrict__ fc2w) {
    int i = blockIdx.x * blockDim.x + threadIdx.x;
    if (i < 27648)            g_wqkv[i]          = __float2half_rn(qkvw[i]);
    else if (i < 36864)       g_wproj[i - 27648] = __float2half_rn(projw[i - 27648]);
    else if (i < 73728)       g_wfc1[i - 36864]  = __float2half_rn(fc1w[i - 36864]);
    else if (i < 110592)      g_wfc2[i - 73728]  = __float2half_rn(fc2w[i - 73728]);
}

// ---------------------------------------------------------------------------
// Prep: log-CPB bias table -> PADDED [49][52] layout, pre-scaled by log2(e)
// ---------------------------------------------------------------------------
__global__ void prep_kernel(const float* __restrict__ w1, const float* __restrict__ b1,
                            const float* __restrict__ w2, const float* __restrict__ b2) {
    int idx = blockIdx.x * blockDim.x + threadIdx.x;
    if (idx >= NTOK * NTOK) return;
    int i = idx / NTOK, j = idx % NTOK;
    float d0 = (float)(i / WIN - j / WIN);
    float d1 = (float)(i % WIN - j % WIN);
    float r0 = copysignf(log1pf(fabsf(d0)), d0);
    float r1 = copysignf(log1pf(fabsf(d1)), d1);
    float a0 = 0.f, a1 = 0.f, a2 = 0.f;
#pragma unroll 4
    for (int m = 0; m < METAH; m++) {
        float hsum = r0 * w1[m] + r1 * w1[METAH + m] + b1[m];
        float gl = gelu_tanh(hsum);
        a0 += gl * w2[m * 3 + 0];
        a1 += gl * w2[m * 3 + 1];
        a2 += gl * w2[m * 3 + 2];
    }
    int o = i * 52 + j;
    g_bias_pad[0 * NTOK * 52 + o] = (a0 + b2[0]) * LOG2E;
    g_bias_pad[1 * NTOK * 52 + o] = (a1 + b2[1]) * LOG2E;
    g_bias_pad[2 * NTOK * 52 + o] = (a2 + b2[2]) * LOG2E;
}

// ---------------------------------------------------------------------------
// LN1 + cyclic shift + window partition -> g_h_h (fp16). One warp per token.
// ---------------------------------------------------------------------------
__global__ __launch_bounds__(256) void ln1_gather_kernel(const float* __restrict__ x,
                                                         const float* __restrict__ g,
                                                         const float* __restrict__ b) {
    int warp = (blockIdx.x * blockDim.x + threadIdx.x) >> 5;
    int lane = threadIdx.x & 31;
    if (warp >= TOKENS) return;
    int w = warp / NTOK, n = warp % NTOK;
    int bimg = w >> 6, wi = w & 63;
    int Y = (wi >> 3) * WIN + n / WIN + SHIFTW; if (Y >= HWDIM) Y -= HWDIM;
    int X = (wi & 7)  * WIN + n % WIN + SHIFTW; if (X >= HWDIM) X -= HWDIM;
    const float* src = x + ((size_t)bimg * (HWDIM * HWDIM) + Y * HWDIM + X) * CCH;
    float v0 = src[lane], v1 = src[lane + 32], v2 = src[lane + 64];
    float s  = warp_sum(v0 + v1 + v2);
    float sq = warp_sum(v0 * v0 + v1 * v1 + v2 * v2);
    float mean = s * (1.f / CCH);
    float var  = sq * (1.f / CCH) - mean * mean;
    float inv  = rsqrtf(var + LN_EPS);
    __half* dst = g_h_h + (size_t)warp * CCH;
    dst[lane]      = __float2half_rn((v0 - mean) * inv * g[lane]      + b[lane]);
    dst[lane + 32] = __float2half_rn((v1 - mean) * inv * g[lane + 32] + b[lane + 32]);
    dst[lane + 64] = __float2half_rn((v2 - mean) * inv * g[lane + 64] + b[lane + 64]);
}

// ---------------------------------------------------------------------------
// Loaders for BN=96 GEMMs (256 threads).  sA stride 64 halves, sB stride 128.
// ---------------------------------------------------------------------------
template <int KT>
__device__ __forceinline__ void load_A96(const __half* __restrict__ A, int m0, int kc,
                                         __half* sAst, int tid) {
#pragma unroll
    for (int i = 0; i < 3; i++) {                 // 128 rows x 6 chunks = 768
        int idx = tid + i * 256;
        int r = idx / 6, c = idx - r * 6;
        cp16(smem_u32(sAst + r * 64 + ((c ^ (r & 7)) * 8)),
             A + (size_t)(m0 + r) * KT + kc * 48 + c * 8);
    }
}
template <int N>
__device__ __forceinline__ void load_B96(const __half* __restrict__ Bw, int n0, int kc,
                                         __half* sB, int tid) {
#pragma unroll
    for (int i = 0; i < 3; i++) {                 // 48 rows x 12 chunks = 576
        int idx = tid + i * 256;
        if (idx < 576) {
            int r = idx / 12, c = idx - r * 12;
            cp16(smem_u32(sB + r * 128 + ((c ^ (r & 7)) * 8)),
                 Bw + (size_t)(kc * 48 + r) * N + n0 + c * 8);
        }
    }
}

// ---------------------------------------------------------------------------
// fp16 GEMM v3: BM=128, BN=96, BK=48, 256 threads (8 warps, 4m x 2n, 32x48
// warp tile), BOTH operands double-buffered in 56KB dynamic smem.
// Schedule identical to the proven BN=48 kernel: stage {A,B} committed as one
// group, next stage prefetched, wait_group 1.
// EPI 0: qkv -> one of g_q/g_k/g_v per block (+sumsq for q,k)
// EPI 2: fc1 -> g_hid = gelu(.)
// EPI 3: fc2 -> d_out += .
// ---------------------------------------------------------------------------
template <int EPI>
__global__ __launch_bounds__(256) void hgemm96_kernel(const float* __restrict__ bias,
                                                      float* __restrict__ out) {
    constexpr int N   = (EPI == 0) ? 288 : (EPI == 2) ? 384 : 96;
    constexpr int KT  = (EPI == 3) ? 384 : 96;
    constexpr int NCH = KT / 48;
    const __half* __restrict__ A =
        (EPI == 0) ? g_h_h : (EPI == 2) ? g_ln2_h : g_hid_h;
    const __half* __restrict__ Bw =
        (EPI == 0) ? g_wqkv : (EPI == 2) ? g_wfc1 : g_wfc2;

    extern __shared__ __align__(16) __half dynsm[];
    __half* sAb[2] = { dynsm,          dynsm + 8192 };          // 128*64 each
    __half* sBb[2] = { dynsm + 16384,  dynsm + 16384 + 6144 };  // 48*128 each
    __shared__ float red[8];

    const int tid  = threadIdx.x;
    const int lane = tid & 31;
    const int wid  = tid >> 5;
    const int wr   = wid >> 1;
    const int wc   = wid & 1;
    const int n0   = blockIdx.x * 96;
    const int m0   = blockIdx.y * 128;

    float acc[2][6][4];
#pragma unroll
    for (int mi = 0; mi < 2; mi++)
#pragma unroll
        for (int ni = 0; ni < 6; ni++)
#pragma unroll
            for (int e = 0; e < 4; e++) acc[mi][ni][e] = 0.f;

    load_A96<KT>(A, m0, 0, sAb[0], tid);
    load_B96<N>(Bw, n0, 0, sBb[0], tid);
    asm volatile("cp.async.commit_group;");

#pragma unroll 1
    for (int kc = 0; kc < NCH; kc++) {
        if (kc + 1 < NCH) {
            load_A96<KT>(A, m0, kc + 1, sAb[(kc + 1) & 1], tid);
            load_B96<N>(Bw, n0, kc + 1, sBb[(kc + 1) & 1], tid);
            asm volatile("cp.async.commit_group;");
            asm volatile("cp.async.wait_group 1;");
        } else {
            asm volatile("cp.async.wait_group 0;");
        }
        __syncthreads();

        const __half* sAc = sAb[kc & 1];
        const __half* sBc = sBb[kc & 1];
#pragma unroll
        for (int ks = 0; ks < 3; ks++) {
            uint32_t af[2][4], bf[6][2];
            const int arow0 = wr * 32 + (lane & 7) + ((lane >> 3) & 1) * 8;
            const int achk  = ks * 2 + (lane >> 4);
#pragma unroll
            for (int mi = 0; mi < 2; mi++) {
                int row = arow0 + mi * 16;
                ldsm4(af[mi][0], af[mi][1], af[mi][2], af[mi][3],
                      smem_u32(sAc + row * 64 + ((achk ^ (row & 7)) * 8)));
            }
            const int brow = ks * 16 + (lane & 7) + ((lane >> 3) & 1) * 8;
#pragma unroll
            for (int p = 0; p < 3; p++) {
                int chk = wc * 6 + 2 * p + (lane >> 4);
                ldsm4t(bf[2 * p][0], bf[2 * p][1], bf[2 * p + 1][0], bf[2 * p + 1][1],
                       smem_u32(sBc + brow * 128 + ((chk ^ (brow & 7)) * 8)));
            }
#pragma unroll
            for (int mi = 0; mi < 2; mi++)
#pragma unroll
                for (int ni = 0; ni < 6; ni++)
                    mma_f16(acc[mi][ni], af[mi], bf[ni]);
        }
        __syncthreads();
    }

    // ---------------- epilogues (proven in R15 pass) ----------------
    const int jb = 2 * (lane & 3);

    if (EPI == 0) {
        float ssum = 0.f;
        const int s_blk = blockIdx.x;                // 0=q 1=k 2=v
        __half* dst = (s_blk == 0) ? g_q_h : (s_blk == 1) ? g_k_h : g_v_h;
        const bool do_sum = (s_blk < 2);
#pragma unroll
        for (int mi = 0; mi < 2; mi++) {
            int r = m0 + wr * 32 + mi * 16 + (lane >> 2);
            size_t rb0 = (size_t)r * CCH;
            size_t rb1 = rb0 + (size_t)8 * CCH;
#pragma unroll
            for (int ni = 0; ni < 6; ni++) {
                int c = wc * 48 + ni * 8 + jb;
                int gc = n0 + c;
                float b0 = bias[gc], b1 = bias[gc + 1];
                float v0 = acc[mi][ni][0] + b0, v1 = acc[mi][ni][1] + b1;
                float v2 = acc[mi][ni][2] + b0, v3 = acc[mi][ni][3] + b1;
                if (do_sum) ssum += v0 * v0 + v1 * v1 + v2 * v2 + v3 * v3;
                *(uint32_t*)&dst[rb0 + c] = pack_h2(v0, v1);
                *(uint32_t*)&dst[rb1 + c] = pack_h2(v2, v3);
            }
        }
        ssum = warp_sum(ssum);
        if (lane == 0) red[wid] = ssum;
        __syncthreads();
        if (tid == 0 && do_sum) {
            float t = 0.f;
#pragma unroll
            for (int i = 0; i < 8; i++) t += red[i];
            if (s_blk == 0) g_pq[blockIdx.y] = t;
            else            g_pk[blockIdx.y] = t;
        }
    } else if (EPI == 2) {
#pragma unroll
        for (int mi = 0; mi < 2; mi++) {
            int r = m0 + wr * 32 + mi * 16 + (lane >> 2);
            size_t rb0 = (size_t)r * MLPH;
            size_t rb1 = rb0 + (size_t)8 * MLPH;
#pragma unroll
            for (int ni = 0; ni < 6; ni++) {
                int c = wc * 48 + ni * 8 + jb;
                int gc = n0 + c;
                float b0 = bias[gc], b1 = bias[gc + 1];
                *(uint32_t*)&g_hid_h[rb0 + gc] =
                    pack_h2(gelu_tanh(acc[mi][ni][0] + b0), gelu_tanh(acc[mi][ni][1] + b1));
                *(uint32_t*)&g_hid_h[rb1 + gc] =
                    pack_h2(gelu_tanh(acc[mi][ni][2] + b0), gelu_tanh(acc[mi][ni][3] + b1));
            }
        }
    } else {
#pragma unroll
        for (int mi = 0; mi < 2; mi++) {
            int r = m0 + wr * 32 + mi * 16 + (lane >> 2);
            size_t rb0 = (size_t)r * CCH;
            size_t rb1 = rb0 + (size_t)8 * CCH;
#pragma unroll
            for (int ni = 0; ni < 6; ni++) {
                int c = wc * 48 + ni * 8 + jb;
                float b0 = bias[c], b1 = bias[c + 1];
                float2 t0 = *(float2*)&out[rb0 + c];
                t0.x += acc[mi][ni][0] + b0; t0.y += acc[mi][ni][1] + b1;
                *(float2*)&out[rb0 + c] = t0;
                float2 t1 = *(float2*)&out[rb1 + c];
                t1.x += acc[mi][ni][2] + b0; t1.y += acc[mi][ni][3] + b1;
                *(float2*)&out[rb1 + c] = t1;
            }
        }
    }
}

// ---------------------------------------------------------------------------
// proj + residual + LN2, fused (unchanged; static smem, proven)
// ---------------------------------------------------------------------------
__global__ __launch_bounds__(256) void proj_ln2_kernel(const float* __restrict__ bias,
                                                       const float* __restrict__ Xres,
                                                       float* __restrict__ out,
                                                       const float* __restrict__ n2g,
                                                       const float* __restrict__ n2b) {
    __shared__ __align__(16) __half sA[2][128 * 64];
    __shared__ __align__(16) __half sB[48 * 128];
    __shared__ float sred[128][2][2];

    const int tid  = threadIdx.x;
    const int lane = tid & 31;
    const int wid  = tid >> 5;
    const int wr   = wid >> 1;
    const int wc   = wid & 1;
    const int m0   = blockIdx.x * 128;

    float acc[2][6][4];
#pragma unroll
    for (int mi = 0; mi < 2; mi++)
#pragma unroll
        for (int ni = 0; ni < 6; ni++)
#pragma unroll
            for (int e = 0; e < 4; e++) acc[mi][ni][e] = 0.f;

    load_A96<96>(g_o_h, m0, 0, sA[0], tid);
    load_B96<96>(g_wproj, 0, 0, sB, tid);
    asm volatile("cp.async.commit_group;");
    load_A96<96>(g_o_h, m0, 1, sA[1], tid);
    asm volatile("cp.async.commit_group;");

#pragma unroll 1
    for (int kc = 0; kc < 2; kc++) {
        if (kc == 0) asm volatile("cp.async.wait_group 1;");
        else         asm volatile("cp.async.wait_group 0;");
        __syncthreads();

#pragma unroll
        for (int ks = 0; ks < 3; ks++) {
            uint32_t af[2][4], bf[6][2];
            const int arow0 = wr * 32 + (lane & 7) + ((lane >> 3) & 1) * 8;
            const int achk  = ks * 2 + (lane >> 4);
#pragma unroll
            for (int mi = 0; mi < 2; mi++) {
                int row = arow0 + mi * 16;
                ldsm4(af[mi][0], af[mi][1], af[mi][2], af[mi][3],
                      smem_u32(&sA[kc][row * 64 + ((achk ^ (row & 7)) * 8)]));
            }
            const int brow = ks * 16 + (lane & 7) + ((lane >> 3) & 1) * 8;
#pragma unroll
            for (int p = 0; p < 3; p++) {
                int chk = wc * 6 + 2 * p + (lane >> 4);
                ldsm4t(bf[2 * p][0], bf[2 * p][1], bf[2 * p + 1][0], bf[2 * p + 1][1],
                       smem_u32(&sB[brow * 128 + ((chk ^ (brow & 7)) * 8)]));
            }
#pragma unroll
            for (int mi = 0; mi < 2; mi++)
#pragma unroll
                for (int ni = 0; ni < 6; ni++)
                    mma_f16(acc[mi][ni], af[mi], bf[ni]);
        }
        __syncthreads();

        if (kc == 0) {
            load_B96<96>(g_wproj, 0, 1, sB, tid);
            asm volatile("cp.async.commit_group;");
        }
    }

    const int jb = 2 * (lane & 3);
    size_t rbase[2][2];
    int    lrow[2][2];
    float  s1[2][2], s2v[2][2];

#pragma unroll
    for (int mi = 0; mi < 2; mi++)
#pragma unroll
        for (int rr = 0; rr < 2; rr++) {
            int row = m0 + wr * 32 + mi * 16 + (lane >> 2) + rr * 8;
            int w_ = row / NTOK, n_ = row - w_ * NTOK;
            int b_ = w_ >> 6, wi_ = w_ & 63;
            int Y = (wi_ >> 3) * WIN + n_ / WIN + SHIFTW; if (Y >= HWDIM) Y -= HWDIM;
            int X = (wi_ & 7)  * WIN + n_ % WIN + SHIFTW; if (X >= HWDIM) X -= HWDIM;
            int lr = b_ * (HWDIM * HWDIM) + Y * HWDIM + X;
            lrow[mi][rr]  = lr;
            rbase[mi][rr] = (size_t)lr * CCH;
            s1[mi][rr] = 0.f; s2v[mi][rr] = 0.f;
        }

#pragma unroll
    for (int mi = 0; mi < 2; mi++)
#pragma unroll
        for (int ni = 0; ni < 6; ni++) {
            int c = wc * 48 + ni * 8 + jb;
            float b0 = bias[c], b1 = bias[c + 1];
#pragma unroll
            for (int rr = 0; rr < 2; rr++) {
                float2 xr = *(const float2*)&Xres[rbase[mi][rr] + c];
                float v0 = xr.x + acc[mi][ni][rr * 2 + 0] + b0;
                float v1 = xr.y + acc[mi][ni][rr * 2 + 1] + b1;
                acc[mi][ni][rr * 2 + 0] = v0;
                acc[mi][ni][rr * 2 + 1] = v1;
                float2 ov; ov.x = v0; ov.y = v1;
                *(float2*)&out[rbase[mi][rr] + c] = ov;
                s1[mi][rr]  += v0 + v1;
                s2v[mi][rr] += v0 * v0 + v1 * v1;
            }
        }

#pragma unroll
    for (int mi = 0; mi < 2; mi++)
#pragma unroll
        for (int rr = 0; rr < 2; rr++) {
            float a = s1[mi][rr], bq = s2v[mi][rr];
            a  += __shfl_xor_sync(0xffffffffu, a, 1);
            a  += __shfl_xor_sync(0xffffffffu, a, 2);
            bq += __shfl_xor_sync(0xffffffffu, bq, 1);
            bq += __shfl_xor_sync(0xffffffffu, bq, 2);
            if ((lane & 3) == 0) {
                int rloc = wr * 32 + mi * 16 + (lane >> 2) + rr * 8;
                sred[rloc][wc][0] = a;
                sred[rloc][wc][1] = bq;
            }
        }
    __syncthreads();

#pragma unroll
    for (int mi = 0; mi < 2; mi++)
#pragma unroll
        for (int rr = 0; rr < 2; rr++) {
            int rloc = wr * 32 + mi * 16 + (lane >> 2) + rr * 8;
            float ts1 = sred[rloc][0][0] + sred[rloc][1][0];
            float ts2 = sred[rloc][0][1] + sred[rloc][1][1];
            float mean = ts1 * (1.f / CCH);
            float var  = ts2 * (1.f / CCH) - mean * mean;
            float inv  = rsqrtf(var + LN_EPS);
            size_t lb = (size_t)lrow[mi][rr] * CCH;
#pragma unroll
            for (int ni = 0; ni < 6; ni++) {
                int c = wc * 48 + ni * 8 + jb;
                float l0 = (acc[mi][ni][rr * 2 + 0] - mean) * inv * n2g[c]     + n2b[c];
                float l1 = (acc[mi][ni][rr * 2 + 1] - mean) * inv * n2g[c + 1] + n2b[c + 1];
                *(uint32_t*)&g_ln2_h[lb + c] = pack_h2(l0, l1);
            }
        }
}

// ---------------------------------------------------------------------------
// Final deterministic reduction of per-block partials (1568 each)
// ---------------------------------------------------------------------------
__global__ __launch_bounds__(256) void redfinal_kernel() {
    float lq = 0.f, lk = 0.f;
    for (int i = threadIdx.x; i < 1568; i += 256) { lq += g_pq[i]; lk += g_pk[i]; }
    lq = warp_sum(lq); lk = warp_sum(lk);
    __shared__ float sq8[8], sk8[8];
    if ((threadIdx.x & 31) == 0) { sq8[threadIdx.x >> 5] = lq; sk8[threadIdx.x >> 5] = lk; }
    __syncthreads();
    if (threadIdx.x == 0) {
        float a = 0.f, b = 0.f;
#pragma unroll
        for (int i = 0; i < 8; i++) { a += sq8[i]; b += sk8[i]; }
        g_sumq = a; g_sumk = b;
    }
}

// ---------------------------------------------------------------------------
// Attention (frozen from R13: low-smem, per-thread L2 bias loads)
// ---------------------------------------------------------------------------
__global__ __launch_bounds__(128) void attn_kernel(const float* __restrict__ tau) {
    __shared__ __align__(16) __half sQ[64 * 40];
    __shared__ __align__(16) __half sK[64 * 40];
    __shared__ __align__(16) __half sV[64 * 40];
    __shared__ int sreg[64];

    const int blk  = blockIdx.x;
    const int w    = blk / NHEADS, hd = blk % NHEADS;
    const int tid  = threadIdx.x;
    const int lane = tid & 31, wid = tid >> 5;
    const size_t tokbase = (size_t)(w * NTOK) * CCH + hd * DHEAD;

    for (int i = tid; i < 196; i += 128) {
        int t = i >> 2, c = i & 3;
        size_t src = tokbase + (size_t)t * CCH + c * 8;
        int o = t * 40 + c * 8;
        *(uint4*)(sQ + o) = *(const uint4*)(g_q_h + src);
        *(uint4*)(sK + o) = *(const uint4*)(g_k_h + src);
    }
    for (int i = tid; i < 256; i += 128) {
        int t = i >> 2, c = i & 3;
        int ts = (t < NTOK) ? t : (NTOK - 1);
        *(uint4*)(sV + t * 40 + c * 8) =
            *(const uint4*)(g_v_h + tokbase + (size_t)ts * CCH + c * 8);
    }
    if (tid < 64) {
        int wi = w & 63;
        int y = (wi >> 3) * WIN + tid / WIN;
        int x = (wi & 7)  * WIN + tid % WIN;
        int ry = (y < 49) ? 0 : ((y < 53) ? 1 : 2);
        int rx = (x < 49) ? 0 : ((x < 53) ? 1 : 2);
        sreg[tid] = ry * 3 + rx;
    }
    __syncthreads();

    const float scale = rsqrtf(g_sumq) * rsqrtf(g_sumk) / fmaxf(tau[0], 0.01f) * LOG2E;

    float s[7][4];
#pragma unroll
    for (int t = 0; t < 7; t++)
#pragma unroll
        for (int e = 0; e < 4; e++) s[t][e] = 0.f;

#pragma unroll
    for (int ks = 0; ks < 2; ks++) {
        uint32_t av[4];
        {
            int arow = wid * 16 + (lane & 7) + ((lane >> 3) & 1) * 8;
            int achk = ks * 2 + (lane >> 4);
            ldsm4(av[0], av[1], av[2], av[3], smem_u32(sQ + arow * 40 + achk * 8));
        }
#pragma unroll
        for (int p = 0; p < 4; p++) {
            uint32_t b0, b1, b2, b3;
            int nrow = p * 16 + (lane & 7) + (lane >> 4) * 8;
            int kchk = ks * 2 + ((lane >> 3) & 1);
            ldsm4(b0, b1, b2, b3, smem_u32(sK + nrow * 40 + kchk * 8));
            uint32_t bp0[2] = {b0, b1};
            mma_f16(s[2 * p], av, bp0);
            if (p < 3) {
                uint32_t bp1[2] = {b2, b3};
                mma_f16(s[2 * p + 1], av, bp1);
            }
        }
    }

    const int r0 = wid * 16 + (lane >> 2);
    const int r1 = r0 + 8;
    const int jb = 2 * (lane & 3);
    const bool v0r = (r0 < NTOK), v1r = (r1 < NTOK);
    const int r0c = v0r ? r0 : 0;
    const int r1c = v1r ? r1 : 0;
    const int ri0 = sreg[r0c];
    const int ri1 = sreg[r1c];

    const float* bh0 = g_bias_pad + hd * NTOK * 52 + r0c * 52;
    const float* bh1 = g_bias_pad + hd * NTOK * 52 + r1c * 52;

    float m0 = -1e30f, m1 = -1e30f;
#pragma unroll
    for (int t = 0; t < 7; t++) {
        int j = t * 8 + jb;
        int jcl = (j <= 48) ? j : 48;
        float2 bb0 = __ldg((const float2*)(bh0 + jcl));
        float2 bb1 = __ldg((const float2*)(bh1 + jcl));
#pragma unroll
        for (int e = 0; e < 2; e++) {
            int jj = j + e;
            bool jv = (jj < NTOK);
            int jc = jv ? jj : (NTOK - 1);
            int rj = sreg[jc];
            float bv0 = (e == 0) ? bb0.x : bb0.y;
            float bv1 = (e == 0) ? bb1.x : bb1.y;
            float x0 = (v0r && jv)
                ? s[t][e] * scale + bv0 + ((rj != ri0) ? MASKC : 0.f)
                : -1e30f;
            float x1 = (v1r && jv)
                ? s[t][e + 2] * scale + bv1 + ((rj != ri1) ? MASKC : 0.f)
                : -1e30f;
            s[t][e] = x0; s[t][e + 2] = x1;
            m0 = fmaxf(m0, x0); m1 = fmaxf(m1, x1);
        }
    }
    m0 = fmaxf(m0, __shfl_xor_sync(0xffffffffu, m0, 1));
    m0 = fmaxf(m0, __shfl_xor_sync(0xffffffffu, m0, 2));
    m1 = fmaxf(m1, __shfl_xor_sync(0xffffffffu, m1, 1));
    m1 = fmaxf(m1, __shfl_xor_sync(0xffffffffu, m1, 2));

    uint32_t s2[8][2];
    float d0 = 0.f, d1 = 0.f;
#pragma unroll
    for (int t = 0; t < 7; t++) {
        uint32_t h0 = h2exp2_u32(pack_h2(s[t][0] - m0, s[t][1] - m0));
        uint32_t h1 = h2exp2_u32(pack_h2(s[t][2] - m1, s[t][3] - m1));
        s2[t][0] = h0; s2[t][1] = h1;
        float2 f0 = h2_to_f2(h0); d0 += f0.x + f0.y;
        float2 f1 = h2_to_f2(h1); d1 += f1.x + f1.y;
    }
    s2[7][0] = 0u; s2[7][1] = 0u;
    d0 += __shfl_xor_sync(0xffffffffu, d0, 1);
    d0 += __shfl_xor_sync(0xffffffffu, d0, 2);
    d1 += __shfl_xor_sync(0xffffffffu, d1, 1);
    d1 += __shfl_xor_sync(0xffffffffu, d1, 2);
    const float i0 = 1.f / d0, i1 = 1.f / d1;

    float o[4][4];
#pragma unroll
    for (int v = 0; v < 4; v++)
#pragma unroll
        for (int e = 0; e < 4; e++) o[v][e] = 0.f;

#pragma unroll
    for (int kt = 0; kt < 4; kt++) {
        uint32_t av[4];
        av[0] = s2[2 * kt][0];
        av[1] = s2[2 * kt][1];
        av[2] = s2[2 * kt + 1][0];
        av[3] = s2[2 * kt + 1][1];
        int vrow = kt * 16 + (lane & 7) + ((lane >> 3) & 1) * 8;
#pragma unroll
        for (int half = 0; half < 2; half++) {
            uint32_t b0, b1, b2, b3;
            int vchk = half * 2 + (lane >> 4);
            ldsm4t(b0, b1, b2, b3, smem_u32(sV + vrow * 40 + vchk * 8));
            uint32_t bp0[2] = {b0, b1};
            uint32_t bp1[2] = {b2, b3};
            mma_f16(o[half * 2],     av, bp0);
            mma_f16(o[half * 2 + 1], av, bp1);
        }
    }

    __syncthreads();
    __half* sO = sQ;
#pragma unroll
    for (int v = 0; v < 4; v++) {
        if (v0r) *(uint32_t*)&sO[r0 * 40 + v * 8 + jb] = pack_h2(o[v][0] * i0, o[v][1] * i0);
        if (v1r) *(uint32_t*)&sO[r1 * 40 + v * 8 + jb] = pack_h2(o[v][2] * i1, o[v][3] * i1);
    }
    __syncthreads();
    for (int i = tid; i < 196; i += 128) {
        int t = i >> 2, c = i & 3;
        *(uint4*)(g_o_h + tokbase + (size_t)t * CCH + c * 8) = *(uint4*)(sO + t * 40 + c * 8);
    }
}

// ---------------------------------------------------------------------------
// Launch (only harness pointers cross the host/device boundary)
// ---------------------------------------------------------------------------
extern "C" void kernel_launch(void* const* d_in, const int* in_sizes, int n_in,
                              void* d_out, int out_size) {
    const float* x      = (const float*)d_in[0];
    const float* n1g    = (const float*)d_in[1];
    const float* n1b    = (const float*)d_in[2];
    const float* qkv_w  = (const float*)d_in[3];
    const float* qkv_b  = (const float*)d_in[4];
    const float* proj_w = (const float*)d_in[5];
    const float* proj_b = (const float*)d_in[6];
    const float* mw1    = (const float*)d_in[7];
    const float* mb1    = (const float*)d_in[8];
    const float* mw2    = (const float*)d_in[9];
    const float* mb2    = (const float*)d_in[10];
    const float* tau    = (const float*)d_in[11];
    const float* n2g    = (const float*)d_in[12];
    const float* n2b    = (const float*)d_in[13];
    const float* fc1w   = (const float*)d_in[14];
    const float* fc1b   = (const float*)d_in[15];
    const float* fc2w   = (const float*)d_in[16];
    const float* fc2b   = (const float*)d_in[17];
    float* out = (float*)d_out;

    // opt-in for 56KB dynamic smem (idempotent attribute set, not an alloc)
    cudaFuncSetAttribute(hgemm96_kernel<0>, cudaFuncAttributeMaxDynamicSharedMemorySize, GEMM_DSMEM);
    cudaFuncSetAttribute(hgemm96_kernel<2>, cudaFuncAttributeMaxDynamicSharedMemorySize, GEMM_DSMEM);
    cudaFuncSetAttribute(hgemm96_kernel<3>, cudaFuncAttributeMaxDynamicSharedMemorySize, GEMM_DSMEM);

    convw_kernel<<<432, 256>>>(qkv_w, proj_w, fc1w, fc2w);
    prep_kernel<<<19, 128>>>(mw1, mb1, mw2, mb2);
    ln1_gather_kernel<<<TOKENS / 8, 256>>>(x, n1g, n1b);

    hgemm96_kernel<0><<<dim3(3, TOKENS / 128), 256, GEMM_DSMEM>>>(qkv_b, nullptr);
    redfinal_kernel<<<1, 256>>>();

    attn_kernel<<<NWTOT * NHEADS, 128>>>(tau);

    proj_ln2_kernel<<<TOKENS / 128, 256>>>(proj_b, x, out, n2g, n2b);

    hgemm96_kernel<2><<<dim3(4, TOKENS / 128), 256, GEMM_DSMEM>>>(fc1b, nullptr);
    hgemm96_kernel<3><<<dim3(1, TOKENS / 128), 256, GEMM_DSMEM>>>(fc2b, out);
}

// round 17
// speedup vs baseline: 1.0606x; 1.0606x over previous
#include <cuda_runtime.h>
#include <cuda_fp16.h>
#include <cstdint>

// ---------------------------------------------------------------------------
// Problem constants
// ---------------------------------------------------------------------------
#define BIMG   64
#define HWDIM  56
#define CCH    96
#define NHEADS 3
#define DHEAD  32
#define WIN    7
#define SHIFTW 3
#define NTOK   49
#define NWIN   64
#define NWTOT  (BIMG * NWIN)      // 4096
#define TOKENS (NWTOT * NTOK)     // 200704
#define MLPH   384
#define METAH  128
#define LN_EPS 1e-5f
#define LOG2E  1.4426950408889634f
#define MASKC  (-100.0f * 1.4426950408889634f)

// ---------------------------------------------------------------------------
// Device scratch (static; cudaMalloc forbidden)
// q/k/v are TOKEN-MAJOR: [token][head*32 + dd]
// ---------------------------------------------------------------------------
__device__ __align__(16) __half g_h_h  [(size_t)TOKENS * CCH];
__device__ __align__(16) __half g_q_h  [(size_t)TOKENS * CCH];
__device__ __align__(16) __half g_k_h  [(size_t)TOKENS * CCH];
__device__ __align__(16) __half g_v_h  [(size_t)TOKENS * CCH];
__device__ __align__(16) __half g_o_h  [(size_t)TOKENS * CCH];
__device__ __align__(16) __half g_ln2_h[(size_t)TOKENS * CCH];
__device__ __align__(16) __half g_hid_h[(size_t)TOKENS * MLPH];
__device__ __align__(16) __half g_wqkv [96 * 288];
__device__ __align__(16) __half g_wproj[96 * 96];
__device__ __align__(16) __half g_wfc1 [96 * 384];
__device__ __align__(16) __half g_wfc2 [384 * 96];
__device__ __align__(16) float g_bias_pad[NHEADS * NTOK * 52];  // padded, *log2e
__device__ float g_pq[3136], g_pk[3136];
__device__ float g_sumq, g_sumk;

// ---------------------------------------------------------------------------
// Helpers
// ---------------------------------------------------------------------------
__device__ __forceinline__ float warp_sum(float v) {
#pragma unroll
    for (int o = 16; o; o >>= 1) v += __shfl_xor_sync(0xffffffffu, v, o);
    return v;
}
__device__ __forceinline__ float tanh_fast(float x) {
    float r;
    asm("tanh.approx.f32 %0, %1;" : "=f"(r) : "f"(x));
    return r;
}
__device__ __forceinline__ float gelu_tanh(float x) {
    float x3 = x * x * x;
    return 0.5f * x * (1.f + tanh_fast(0.7978845608028654f * (x + 0.044715f * x3)));
}
__device__ __forceinline__ uint32_t smem_u32(const void* p) {
    return (uint32_t)__cvta_generic_to_shared(p);
}
__device__ __forceinline__ void cp16(uint32_t dst, const void* src) {
    asm volatile("cp.async.cg.shared.global [%0], [%1], 16;" :: "r"(dst), "l"(src));
}
__device__ __forceinline__ void ldsm4(uint32_t& r0, uint32_t& r1, uint32_t& r2, uint32_t& r3, uint32_t a) {
    asm volatile("ldmatrix.sync.aligned.m8n8.x4.shared.b16 {%0,%1,%2,%3}, [%4];"
                 : "=r"(r0), "=r"(r1), "=r"(r2), "=r"(r3) : "r"(a));
}
__device__ __forceinline__ void ldsm4t(uint32_t& r0, uint32_t& r1, uint32_t& r2, uint32_t& r3, uint32_t a) {
    asm volatile("ldmatrix.sync.aligned.m8n8.x4.trans.shared.b16 {%0,%1,%2,%3}, [%4];"
                 : "=r"(r0), "=r"(r1), "=r"(r2), "=r"(r3) : "r"(a));
}
__device__ __forceinline__ void mma_f16(float c[4], const uint32_t a[4], const uint32_t b[2]) {
    asm volatile(
        "mma.sync.aligned.m16n8k16.row.col.f32.f16.f16.f32 "
        "{%0,%1,%2,%3}, {%4,%5,%6,%7}, {%8,%9}, {%0,%1,%2,%3};"
        : "+f"(c[0]), "+f"(c[1]), "+f"(c[2]), "+f"(c[3])
        : "r"(a[0]), "r"(a[1]), "r"(a[2]), "r"(a[3]), "r"(b[0]), "r"(b[1]));
}
__device__ __forceinline__ uint32_t pack_h2(float lo, float hi) {
    __half2 h = __floats2half2_rn(lo, hi);
    return (uint32_t)__half_as_ushort(__low2half(h)) |
           ((uint32_t)__half_as_ushort(__high2half(h)) << 16);
}
__device__ __forceinline__ uint32_t h2exp2_u32(uint32_t x) {
    uint32_t r;
    asm("ex2.approx.f16x2 %0, %1;" : "=r"(r) : "r"(x));
    return r;
}
__device__ __forceinline__ float2 h2_to_f2(uint32_t u) {
    float lo = __half2float(__ushort_as_half((unsigned short)(u & 0xffffu)));
    float hi = __half2float(__ushort_as_half((unsigned short)(u >> 16)));
    return make_float2(lo, hi);
}

// ---------------------------------------------------------------------------
// Fused setup: blocks 0..431 convert weights fp32->fp16; blocks 432+ build
// the padded log-CPB bias table.  The two jobs touch disjoint data.
// ---------------------------------------------------------------------------
__global__ void setup_kernel(const float* __restrict__ qkvw, const float* __restrict__ projw,
                             const float* __restrict__ fc1w, const float* __restrict__ fc2w,
                             const float* __restrict__ w1, const float* __restrict__ b1,
                             const float* __restrict__ w2, const float* __restrict__ b2) {
    if (blockIdx.x < 432) {
        int i = blockIdx.x * 256 + threadIdx.x;
        if (i < 27648)            g_wqkv[i]          = __float2half_rn(qkvw[i]);
        else if (i < 36864)       g_wproj[i - 27648] = __float2half_rn(projw[i - 27648]);
        else if (i < 73728)       g_wfc1[i - 36864]  = __float2half_rn(fc1w[i - 36864]);
        else if (i < 110592)      g_wfc2[i - 73728]  = __float2half_rn(fc2w[i - 73728]);
    } else {
        int idx = (blockIdx.x - 432) * 256 + threadIdx.x;
        if (idx >= NTOK * NTOK) return;
        int i = idx / NTOK, j = idx % NTOK;
        float d0 = (float)(i / WIN - j / WIN);
        float d1 = (float)(i % WIN - j % WIN);
        float r0 = copysignf(log1pf(fabsf(d0)), d0);
        float r1 = copysignf(log1pf(fabsf(d1)), d1);
        float a0 = 0.f, a1 = 0.f, a2 = 0.f;
#pragma unroll 4
        for (int m = 0; m < METAH; m++) {
            float hsum = r0 * w1[m] + r1 * w1[METAH + m] + b1[m];
            float gl = gelu_tanh(hsum);
            a0 += gl * w2[m * 3 + 0];
            a1 += gl * w2[m * 3 + 1];
            a2 += gl * w2[m * 3 + 2];
        }
        int o = i * 52 + j;
        g_bias_pad[0 * NTOK * 52 + o] = (a0 + b2[0]) * LOG2E;
        g_bias_pad[1 * NTOK * 52 + o] = (a1 + b2[1]) * LOG2E;
        g_bias_pad[2 * NTOK * 52 + o] = (a2 + b2[2]) * LOG2E;
    }
}

// ---------------------------------------------------------------------------
// LN1 + cyclic shift + window partition -> g_h_h (fp16). One warp per token.
// ---------------------------------------------------------------------------
__global__ __launch_bounds__(256) void ln1_gather_kernel(const float* __restrict__ x,
                                                         const float* __restrict__ g,
                                                         const float* __restrict__ b) {
    int warp = (blockIdx.x * blockDim.x + threadIdx.x) >> 5;
    int lane = threadIdx.x & 31;
    if (warp >= TOKENS) return;
    int w = warp / NTOK, n = warp % NTOK;
    int bimg = w >> 6, wi = w & 63;
    int Y = (wi >> 3) * WIN + n / WIN + SHIFTW; if (Y >= HWDIM) Y -= HWDIM;
    int X = (wi & 7)  * WIN + n % WIN + SHIFTW; if (X >= HWDIM) X -= HWDIM;
    const float* src = x + ((size_t)bimg * (HWDIM * HWDIM) + Y * HWDIM + X) * CCH;
    float v0 = src[lane], v1 = src[lane + 32], v2 = src[lane + 64];
    float s  = warp_sum(v0 + v1 + v2);
    float sq = warp_sum(v0 * v0 + v1 * v1 + v2 * v2);
    float mean = s * (1.f / CCH);
    float var  = sq * (1.f / CCH) - mean * mean;
    float inv  = rsqrtf(var + LN_EPS);
    __half* dst = g_h_h + (size_t)warp * CCH;
    dst[lane]      = __float2half_rn((v0 - mean) * inv * g[lane]      + b[lane]);
    dst[lane + 32] = __float2half_rn((v1 - mean) * inv * g[lane + 32] + b[lane + 32]);
    dst[lane + 64] = __float2half_rn((v2 - mean) * inv * g[lane + 64] + b[lane + 64]);
}

// ---------------------------------------------------------------------------
// GEMM stage loader for 128 threads (sA/sB stride 64 halves)
// ---------------------------------------------------------------------------
template <int N, int KT>
__device__ __forceinline__ void gemm_load_stage(const __half* __restrict__ A,
                                                const __half* __restrict__ Bw,
                                                int m0, int n0, int kc,
                                                __half* sAst, __half* sBst, int tid) {
#pragma unroll
    for (int i = 0; i < 6; i++) {
        int idx = tid + i * 128;
        int r = idx / 6, c = idx - r * 6;
        const __half* src = A + (size_t)(m0 + r) * KT + kc * 48 + c * 8;
        cp16(smem_u32(sAst + r * 64 + ((c ^ (r & 7)) * 8)), src);
    }
#pragma unroll
    for (int i = 0; i < 3; i++) {
        int idx = tid + i * 128;
        if (idx < 288) {
            int r = idx / 6, c = idx - r * 6;
            const __half* src = Bw + (size_t)(kc * 48 + r) * N + n0 + c * 8;
            cp16(smem_u32(sBst + r * 64 + ((c ^ (r & 7)) * 8)), src);
        }
    }
    asm volatile("cp.async.commit_group;");
}

// ---------------------------------------------------------------------------
// fp16 tensor-core GEMM (qkv / fc1 / fc2) — the proven R13 configuration.
// BM=128, BN=48, BK=48, 2-stage cp.async, 4 warps, warp tile 32x48.
// ---------------------------------------------------------------------------
template <int EPI>
__global__ __launch_bounds__(128) void hgemm_kernel(const float* __restrict__ bias,
                                                    float* __restrict__ out) {
    constexpr int N   = (EPI == 0) ? 288 : (EPI == 2) ? 384 : 96;
    constexpr int KT  = (EPI == 3) ? 384 : 96;
    constexpr int NCH = KT / 48;
    const __half* __restrict__ A =
        (EPI == 0) ? g_h_h : (EPI == 2) ? g_ln2_h : g_hid_h;
    const __half* __restrict__ Bw =
        (EPI == 0) ? g_wqkv : (EPI == 2) ? g_wfc1 : g_wfc2;

    __shared__ __align__(16) __half sA[2][128 * 64];
    __shared__ __align__(16) __half sB[2][48 * 64];
    __shared__ float red[4];

    const int tid  = threadIdx.x;
    const int lane = tid & 31;
    const int wid  = tid >> 5;
    const int n0   = blockIdx.x * 48;
    const int m0   = blockIdx.y * 128;

    float acc[2][6][4];
#pragma unroll
    for (int mi = 0; mi < 2; mi++)
#pragma unroll
        for (int ni = 0; ni < 6; ni++)
#pragma unroll
            for (int e = 0; e < 4; e++) acc[mi][ni][e] = 0.f;

    gemm_load_stage<N, KT>(A, Bw, m0, n0, 0, sA[0], sB[0], tid);

#pragma unroll 1
    for (int kc = 0; kc < NCH; kc++) {
        if (kc + 1 < NCH) {
            gemm_load_stage<N, KT>(A, Bw, m0, n0, kc + 1, sA[(kc + 1) & 1], sB[(kc + 1) & 1], tid);
            asm volatile("cp.async.wait_group 1;");
        } else {
            asm volatile("cp.async.wait_group 0;");
        }
        __syncthreads();

        const int st = kc & 1;
#pragma unroll
        for (int ks = 0; ks < 3; ks++) {
            uint32_t af[2][4], bf[6][2];
            const int arow0 = wid * 32 + (lane & 7) + ((lane >> 3) & 1) * 8;
            const int achk  = ks * 2 + (lane >> 4);
#pragma unroll
            for (int mi = 0; mi < 2; mi++) {
                int row = arow0 + mi * 16;
                ldsm4(af[mi][0], af[mi][1], af[mi][2], af[mi][3],
                      smem_u32(&sA[st][row * 64 + ((achk ^ (row & 7)) * 8)]));
            }
            const int brow = ks * 16 + (lane & 7) + ((lane >> 3) & 1) * 8;
#pragma unroll
            for (int p = 0; p < 3; p++) {
                int chk = 2 * p + (lane >> 4);
                ldsm4t(bf[2 * p][0], bf[2 * p][1], bf[2 * p + 1][0], bf[2 * p + 1][1],
                       smem_u32(&sB[st][brow * 64 + ((chk ^ (brow & 7)) * 8)]));
            }
#pragma unroll
            for (int mi = 0; mi < 2; mi++)
#pragma unroll
                for (int ni = 0; ni < 6; ni++)
                    mma_f16(acc[mi][ni], af[mi], bf[ni]);
        }
        __syncthreads();
    }

    const int jb = 2 * (lane & 3);

    if (EPI == 0) {
        float ssum = 0.f;
        const int s_blk = n0 / 96;
        const int cm0   = (n0 - s_blk * 96) + jb;
        __half* dst = (s_blk == 0) ? g_q_h : (s_blk == 1) ? g_k_h : g_v_h;
        const bool do_sum = (n0 < 192);
#pragma unroll
        for (int mi = 0; mi < 2; mi++) {
            int r = m0 + wid * 32 + mi * 16 + (lane >> 2);
            size_t rb0 = (size_t)r * CCH;
            size_t rb1 = rb0 + (size_t)8 * CCH;
#pragma unroll
            for (int ni = 0; ni < 6; ni++) {
                int c = n0 + ni * 8 + jb;
                float b0 = bias[c], b1 = bias[c + 1];
                float v0 = acc[mi][ni][0] + b0, v1 = acc[mi][ni][1] + b1;
                float v2 = acc[mi][ni][2] + b0, v3 = acc[mi][ni][3] + b1;
                if (do_sum) ssum += v0 * v0 + v1 * v1 + v2 * v2 + v3 * v3;
                int cm = cm0 + ni * 8;
                *(uint32_t*)&dst[rb0 + cm] = pack_h2(v0, v1);
                *(uint32_t*)&dst[rb1 + cm] = pack_h2(v2, v3);
            }
        }
        ssum = warp_sum(ssum);
        if (lane == 0) red[wid] = ssum;
        __syncthreads();
        if (tid == 0 && do_sum) {
            float t = red[0] + red[1] + red[2] + red[3];
            if (n0 < 96) g_pq[blockIdx.y * 2 + blockIdx.x] = t;
            else         g_pk[blockIdx.y * 2 + (blockIdx.x - 2)] = t;
        }
    } else if (EPI == 2) {
#pragma unroll
        for (int mi = 0; mi < 2; mi++) {
            int r = m0 + wid * 32 + mi * 16 + (lane >> 2);
            size_t rb0 = (size_t)r * MLPH;
            size_t rb1 = rb0 + (size_t)8 * MLPH;
#pragma unroll
            for (int ni = 0; ni < 6; ni++) {
                int c = n0 + ni * 8 + jb;
                float b0 = bias[c], b1 = bias[c + 1];
                *(uint32_t*)&g_hid_h[rb0 + c] =
                    pack_h2(gelu_tanh(acc[mi][ni][0] + b0), gelu_tanh(acc[mi][ni][1] + b1));
                *(uint32_t*)&g_hid_h[rb1 + c] =
                    pack_h2(gelu_tanh(acc[mi][ni][2] + b0), gelu_tanh(acc[mi][ni][3] + b1));
            }
        }
    } else {
#pragma unroll
        for (int mi = 0; mi < 2; mi++) {
            int r = m0 + wid * 32 + mi * 16 + (lane >> 2);
            size_t rb0 = (size_t)r * CCH;
            size_t rb1 = rb0 + (size_t)8 * CCH;
#pragma unroll
            for (int ni = 0; ni < 6; ni++) {
                int c = n0 + ni * 8 + jb;
                float b0 = bias[c], b1 = bias[c + 1];
                float2 t0 = *(float2*)&out[rb0 + c];
                t0.x += acc[mi][ni][0] + b0; t0.y += acc[mi][ni][1] + b1;
                *(float2*)&out[rb0 + c] = t0;
                float2 t1 = *(float2*)&out[rb1 + c];
                t1.x += acc[mi][ni][2] + b0; t1.y += acc[mi][ni][3] + b1;
                *(float2*)&out[rb1 + c] = t1;
            }
        }
    }
}

// ---------------------------------------------------------------------------
// proj + residual + LN2, fused (R11/R13 proven version, static smem)
// ---------------------------------------------------------------------------
__global__ __launch_bounds__(256) void proj_ln2_kernel(const float* __restrict__ bias,
                                                       const float* __restrict__ Xres,
                                                       float* __restrict__ out,
                                                       const float* __restrict__ n2g,
                                                       const float* __restrict__ n2b) {
    __shared__ __align__(16) __half sA[2][128 * 64];
    __shared__ __align__(16) __half sB[48 * 128];
    __shared__ float sred[128][2][2];

    const int tid  = threadIdx.x;
    const int lane = tid & 31;
    const int wid  = tid >> 5;
    const int wr   = wid >> 1;
    const int wc   = wid & 1;
    const int m0   = blockIdx.x * 128;

    float acc[2][6][4];
#pragma unroll
    for (int mi = 0; mi < 2; mi++)
#pragma unroll
        for (int ni = 0; ni < 6; ni++)
#pragma unroll
            for (int e = 0; e < 4; e++) acc[mi][ni][e] = 0.f;

#pragma unroll
    for (int i = 0; i < 3; i++) {
        int idx = tid + i * 256;
        int r = idx / 6, c = idx - r * 6;
        cp16(smem_u32(&sA[0][r * 64 + ((c ^ (r & 7)) * 8)]),
             g_o_h + (size_t)(m0 + r) * 96 + c * 8);
    }
#pragma unroll
    for (int i = 0; i < 3; i++) {
        int idx = tid + i * 256;
        if (idx < 576) {
            int r = idx / 12, c = idx - r * 12;
            cp16(smem_u32(&sB[r * 128 + ((c ^ (r & 7)) * 8)]),
                 g_wproj + (size_t)r * 96 + c * 8);
        }
    }
    asm volatile("cp.async.commit_group;");
#pragma unroll
    for (int i = 0; i < 3; i++) {
        int idx = tid + i * 256;
        int r = idx / 6, c = idx - r * 6;
        cp16(smem_u32(&sA[1][r * 64 + ((c ^ (r & 7)) * 8)]),
             g_o_h + (size_t)(m0 + r) * 96 + 48 + c * 8);
    }
    asm volatile("cp.async.commit_group;");

#pragma unroll 1
    for (int kc = 0; kc < 2; kc++) {
        if (kc == 0) asm volatile("cp.async.wait_group 1;");
        else         asm volatile("cp.async.wait_group 0;");
        __syncthreads();

#pragma unroll
        for (int ks = 0; ks < 3; ks++) {
            uint32_t af[2][4], bf[6][2];
            const int arow0 = wr * 32 + (lane & 7) + ((lane >> 3) & 1) * 8;
            const int achk  = ks * 2 + (lane >> 4);
#pragma unroll
            for (int mi = 0; mi < 2; mi++) {
                int row = arow0 + mi * 16;
                ldsm4(af[mi][0], af[mi][1], af[mi][2], af[mi][3],
                      smem_u32(&sA[kc][row * 64 + ((achk ^ (row & 7)) * 8)]));
            }
            const int brow = ks * 16 + (lane & 7) + ((lane >> 3) & 1) * 8;
#pragma unroll
            for (int p = 0; p < 3; p++) {
                int chk = wc * 6 + 2 * p + (lane >> 4);
                ldsm4t(bf[2 * p][0], bf[2 * p][1], bf[2 * p + 1][0], bf[2 * p + 1][1],
                       smem_u32(&sB[brow * 128 + ((chk ^ (brow & 7)) * 8)]));
            }
#pragma unroll
            for (int mi = 0; mi < 2; mi++)
#pragma unroll
                for (int ni = 0; ni < 6; ni++)
                    mma_f16(acc[mi][ni], af[mi], bf[ni]);
        }
        __syncthreads();

        if (kc == 0) {
#pragma unroll
            for (int i = 0; i < 3; i++) {
                int idx = tid + i * 256;
                if (idx < 576) {
                    int r = idx / 12, c = idx - r * 12;
                    cp16(smem_u32(&sB[r * 128 + ((c ^ (r & 7)) * 8)]),
                         g_wproj + (size_t)(48 + r) * 96 + c * 8);
                }
            }
            asm volatile("cp.async.commit_group;");
        }
    }

    const int jb = 2 * (lane & 3);
    size_t rbase[2][2];
    int    lrow[2][2];
    float  s1[2][2], s2v[2][2];

#pragma unroll
    for (int mi = 0; mi < 2; mi++)
#pragma unroll
        for (int rr = 0; rr < 2; rr++) {
            int row = m0 + wr * 32 + mi * 16 + (lane >> 2) + rr * 8;
            int w_ = row / NTOK, n_ = row - w_ * NTOK;
            int b_ = w_ >> 6, wi_ = w_ & 63;
            int Y = (wi_ >> 3) * WIN + n_ / WIN + SHIFTW; if (Y >= HWDIM) Y -= HWDIM;
            int X = (wi_ & 7)  * WIN + n_ % WIN + SHIFTW; if (X >= HWDIM) X -= HWDIM;
            int lr = b_ * (HWDIM * HWDIM) + Y * HWDIM + X;
            lrow[mi][rr]  = lr;
            rbase[mi][rr] = (size_t)lr * CCH;
            s1[mi][rr] = 0.f; s2v[mi][rr] = 0.f;
        }

#pragma unroll
    for (int mi = 0; mi < 2; mi++)
#pragma unroll
        for (int ni = 0; ni < 6; ni++) {
            int c = wc * 48 + ni * 8 + jb;
            float b0 = bias[c], b1 = bias[c + 1];
#pragma unroll
            for (int rr = 0; rr < 2; rr++) {
                float2 xr = *(const float2*)&Xres[rbase[mi][rr] + c];
                float v0 = xr.x + acc[mi][ni][rr * 2 + 0] + b0;
                float v1 = xr.y + acc[mi][ni][rr * 2 + 1] + b1;
                acc[mi][ni][rr * 2 + 0] = v0;
                acc[mi][ni][rr * 2 + 1] = v1;
                float2 ov; ov.x = v0; ov.y = v1;
                *(float2*)&out[rbase[mi][rr] + c] = ov;
                s1[mi][rr]  += v0 + v1;
                s2v[mi][rr] += v0 * v0 + v1 * v1;
            }
        }

#pragma unroll
    for (int mi = 0; mi < 2; mi++)
#pragma unroll
        for (int rr = 0; rr < 2; rr++) {
            float a = s1[mi][rr], bq = s2v[mi][rr];
            a  += __shfl_xor_sync(0xffffffffu, a, 1);
            a  += __shfl_xor_sync(0xffffffffu, a, 2);
            bq += __shfl_xor_sync(0xffffffffu, bq, 1);
            bq += __shfl_xor_sync(0xffffffffu, bq, 2);
            if ((lane & 3) == 0) {
                int rloc = wr * 32 + mi * 16 + (lane >> 2) + rr * 8;
                sred[rloc][wc][0] = a;
                sred[rloc][wc][1] = bq;
            }
        }
    __syncthreads();

#pragma unroll
    for (int mi = 0; mi < 2; mi++)
#pragma unroll
        for (int rr = 0; rr < 2; rr++) {
            int rloc = wr * 32 + mi * 16 + (lane >> 2) + rr * 8;
            float ts1 = sred[rloc][0][0] + sred[rloc][1][0];
            float ts2 = sred[rloc][0][1] + sred[rloc][1][1];
            float mean = ts1 * (1.f / CCH);
            float var  = ts2 * (1.f / CCH) - mean * mean;
            float inv  = rsqrtf(var + LN_EPS);
            size_t lb = (size_t)lrow[mi][rr] * CCH;
#pragma unroll
            for (int ni = 0; ni < 6; ni++) {
                int c = wc * 48 + ni * 8 + jb;
                float l0 = (acc[mi][ni][rr * 2 + 0] - mean) * inv * n2g[c]     + n2b[c];
                float l1 = (acc[mi][ni][rr * 2 + 1] - mean) * inv * n2g[c + 1] + n2b[c + 1];
                *(uint32_t*)&g_ln2_h[lb + c] = pack_h2(l0, l1);
            }
        }
}

// ---------------------------------------------------------------------------
// Final deterministic reduction of per-block partials
// ---------------------------------------------------------------------------
__global__ __launch_bounds__(256) void redfinal_kernel() {
    float lq = 0.f, lk = 0.f;
    for (int i = threadIdx.x; i < 3136; i += 256) { lq += g_pq[i]; lk += g_pk[i]; }
    lq = warp_sum(lq); lk = warp_sum(lk);
    __shared__ float sq8[8], sk8[8];
    if ((threadIdx.x & 31) == 0) { sq8[threadIdx.x >> 5] = lq; sk8[threadIdx.x >> 5] = lk; }
    __syncthreads();
    if (threadIdx.x == 0) {
        float a = 0.f, b = 0.f;
#pragma unroll
        for (int i = 0; i < 8; i++) { a += sq8[i]; b += sk8[i]; }
        g_sumq = a; g_sumk = b;
    }
}

// ---------------------------------------------------------------------------
// Attention (R13 champion: low-smem, per-thread L2 bias loads)
// ---------------------------------------------------------------------------
__global__ __launch_bounds__(128) void attn_kernel(const float* __restrict__ tau) {
    __shared__ __align__(16) __half sQ[64 * 40];
    __shared__ __align__(16) __half sK[64 * 40];
    __shared__ __align__(16) __half sV[64 * 40];
    __shared__ int sreg[64];

    const int blk  = blockIdx.x;
    const int w    = blk / NHEADS, hd = blk % NHEADS;
    const int tid  = threadIdx.x;
    const int lane = tid & 31, wid = tid >> 5;
    const size_t tokbase = (size_t)(w * NTOK) * CCH + hd * DHEAD;

    for (int i = tid; i < 196; i += 128) {
        int t = i >> 2, c = i & 3;
        size_t src = tokbase + (size_t)t * CCH + c * 8;
        int o = t * 40 + c * 8;
        *(uint4*)(sQ + o) = *(const uint4*)(g_q_h + src);
        *(uint4*)(sK + o) = *(const uint4*)(g_k_h + src);
    }
    for (int i = tid; i < 256; i += 128) {
        int t = i >> 2, c = i & 3;
        int ts = (t < NTOK) ? t : (NTOK - 1);
        *(uint4*)(sV + t * 40 + c * 8) =
            *(const uint4*)(g_v_h + tokbase + (size_t)ts * CCH + c * 8);
    }
    if (tid < 64) {
        int wi = w & 63;
        int y = (wi >> 3) * WIN + tid / WIN;
        int x = (wi & 7)  * WIN + tid % WIN;
        int ry = (y < 49) ? 0 : ((y < 53) ? 1 : 2);
        int rx = (x < 49) ? 0 : ((x < 53) ? 1 : 2);
        sreg[tid] = ry * 3 + rx;
    }
    __syncthreads();

    const float scale = rsqrtf(g_sumq) * rsqrtf(g_sumk) / fmaxf(tau[0], 0.01f) * LOG2E;

    float s[7][4];
#pragma unroll
    for (int t = 0; t < 7; t++)
#pragma unroll
        for (int e = 0; e < 4; e++) s[t][e] = 0.f;

#pragma unroll
    for (int ks = 0; ks < 2; ks++) {
        uint32_t av[4];
        {
            int arow = wid * 16 + (lane & 7) + ((lane >> 3) & 1) * 8;
            int achk = ks * 2 + (lane >> 4);
            ldsm4(av[0], av[1], av[2], av[3], smem_u32(sQ + arow * 40 + achk * 8));
        }
#pragma unroll
        for (int p = 0; p < 4; p++) {
            uint32_t b0, b1, b2, b3;
            int nrow = p * 16 + (lane & 7) + (lane >> 4) * 8;
            int kchk = ks * 2 + ((lane >> 3) & 1);
            ldsm4(b0, b1, b2, b3, smem_u32(sK + nrow * 40 + kchk * 8));
            uint32_t bp0[2] = {b0, b1};
            mma_f16(s[2 * p], av, bp0);
            if (p < 3) {
                uint32_t bp1[2] = {b2, b3};
                mma_f16(s[2 * p + 1], av, bp1);
            }
        }
    }

    const int r0 = wid * 16 + (lane >> 2);
    const int r1 = r0 + 8;
    const int jb = 2 * (lane & 3);
    const bool v0r = (r0 < NTOK), v1r = (r1 < NTOK);
    const int r0c = v0r ? r0 : 0;
    const int r1c = v1r ? r1 : 0;
    const int ri0 = sreg[r0c];
    const int ri1 = sreg[r1c];

    const float* bh0 = g_bias_pad + hd * NTOK * 52 + r0c * 52;
    const float* bh1 = g_bias_pad + hd * NTOK * 52 + r1c * 52;

    float m0 = -1e30f, m1 = -1e30f;
#pragma unroll
    for (int t = 0; t < 7; t++) {
        int j = t * 8 + jb;
        int jcl = (j <= 48) ? j : 48;
        float2 bb0 = __ldg((const float2*)(bh0 + jcl));
        float2 bb1 = __ldg((const float2*)(bh1 + jcl));
#pragma unroll
        for (int e = 0; e < 2; e++) {
            int jj = j + e;
            bool jv = (jj < NTOK);
            int jc = jv ? jj : (NTOK - 1);
            int rj = sreg[jc];
            float bv0 = (e == 0) ? bb0.x : bb0.y;
            float bv1 = (e == 0) ? bb1.x : bb1.y;
            float x0 = (v0r && jv)
                ? s[t][e] * scale + bv0 + ((rj != ri0) ? MASKC : 0.f)
                : -1e30f;
            float x1 = (v1r && jv)
                ? s[t][e + 2] * scale + bv1 + ((rj != ri1) ? MASKC : 0.f)
                : -1e30f;
            s[t][e] = x0; s[t][e + 2] = x1;
            m0 = fmaxf(m0, x0); m1 = fmaxf(m1, x1);
        }
    }
    m0 = fmaxf(m0, __shfl_xor_sync(0xffffffffu, m0, 1));
    m0 = fmaxf(m0, __shfl_xor_sync(0xffffffffu, m0, 2));
    m1 = fmaxf(m1, __shfl_xor_sync(0xffffffffu, m1, 1));
    m1 = fmaxf(m1, __shfl_xor_sync(0xffffffffu, m1, 2));

    uint32_t s2[8][2];
    float d0 = 0.f, d1 = 0.f;
#pragma unroll
    for (int t = 0; t < 7; t++) {
        uint32_t h0 = h2exp2_u32(pack_h2(s[t][0] - m0, s[t][1] - m0));
        uint32_t h1 = h2exp2_u32(pack_h2(s[t][2] - m1, s[t][3] - m1));
        s2[t][0] = h0; s2[t][1] = h1;
        float2 f0 = h2_to_f2(h0); d0 += f0.x + f0.y;
        float2 f1 = h2_to_f2(h1); d1 += f1.x + f1.y;
    }
    s2[7][0] = 0u; s2[7][1] = 0u;
    d0 += __shfl_xor_sync(0xffffffffu, d0, 1);
    d0 += __shfl_xor_sync(0xffffffffu, d0, 2);
    d1 += __shfl_xor_sync(0xffffffffu, d1, 1);
    d1 += __shfl_xor_sync(0xffffffffu, d1, 2);
    const float i0 = 1.f / d0, i1 = 1.f / d1;

    float o[4][4];
#pragma unroll
    for (int v = 0; v < 4; v++)
#pragma unroll
        for (int e = 0; e < 4; e++) o[v][e] = 0.f;

#pragma unroll
    for (int kt = 0; kt < 4; kt++) {
        uint32_t av[4];
        av[0] = s2[2 * kt][0];
        av[1] = s2[2 * kt][1];
        av[2] = s2[2 * kt + 1][0];
        av[3] = s2[2 * kt + 1][1];
        int vrow = kt * 16 + (lane & 7) + ((lane >> 3) & 1) * 8;
#pragma unroll
        for (int half = 0; half < 2; half++) {
            uint32_t b0, b1, b2, b3;
            int vchk = half * 2 + (lane >> 4);
            ldsm4t(b0, b1, b2, b3, smem_u32(sV + vrow * 40 + vchk * 8));
            uint32_t bp0[2] = {b0, b1};
            uint32_t bp1[2] = {b2, b3};
            mma_f16(o[half * 2],     av, bp0);
            mma_f16(o[half * 2 + 1], av, bp1);
        }
    }

    __syncthreads();
    __half* sO = sQ;
#pragma unroll
    for (int v = 0; v < 4; v++) {
        if (v0r) *(uint32_t*)&sO[r0 * 40 + v * 8 + jb] = pack_h2(o[v][0] * i0, o[v][1] * i0);
        if (v1r) *(uint32_t*)&sO[r1 * 40 + v * 8 + jb] = pack_h2(o[v][2] * i1, o[v][3] * i1);
    }
    __syncthreads();
    for (int i = tid; i < 196; i += 128) {
        int t = i >> 2, c = i & 3;
        *(uint4*)(g_o_h + tokbase + (size_t)t * CCH + c * 8) = *(uint4*)(sO + t * 40 + c * 8);
    }
}

// ---------------------------------------------------------------------------
// Launch (only harness pointers cross the host/device boundary)
// ---------------------------------------------------------------------------
extern "C" void kernel_launch(void* const* d_in, const int* in_sizes, int n_in,
                              void* d_out, int out_size) {
    const float* x      = (const float*)d_in[0];
    const float* n1g    = (const float*)d_in[1];
    const float* n1b    = (const float*)d_in[2];
    const float* qkv_w  = (const float*)d_in[3];
    const float* qkv_b  = (const float*)d_in[4];
    const float* proj_w = (const float*)d_in[5];
    const float* proj_b = (const float*)d_in[6];
    const float* mw1    = (const float*)d_in[7];
    const float* mb1    = (const float*)d_in[8];
    const float* mw2    = (const float*)d_in[9];
    const float* mb2    = (const float*)d_in[10];
    const float* tau    = (const float*)d_in[11];
    const float* n2g    = (const float*)d_in[12];
    const float* n2b    = (const float*)d_in[13];
    const float* fc1w   = (const float*)d_in[14];
    const float* fc1b   = (const float*)d_in[15];
    const float* fc2w   = (const float*)d_in[16];
    const float* fc2b   = (const float*)d_in[17];
    float* out = (float*)d_out;

    setup_kernel<<<442, 256>>>(qkv_w, proj_w, fc1w, fc2w, mw1, mb1, mw2, mb2);
    ln1_gather_kernel<<<TOKENS / 8, 256>>>(x, n1g, n1b);

    hgemm_kernel<0><<<dim3(6, TOKENS / 128), 128>>>(qkv_b, nullptr);
    redfinal_kernel<<<1, 256>>>();

    attn_kernel<<<NWTOT * NHEADS, 128>>>(tau);

    proj_ln2_kernel<<<TOKENS / 128, 256>>>(proj_b, x, out, n2g, n2b);

    hgemm_kernel<2><<<dim3(8, TOKENS / 128), 128>>>(fc1b, nullptr);
    hgemm_kernel<3><<<dim3(2, TOKENS / 128), 128>>>(fc2b, out);
}